// round 1
// baseline (speedup 1.0000x reference)
#include <cuda_runtime.h>
#include <math.h>

// ---------------------------------------------------------------------------
// TreeGetter: 11-level conv halving tree.
//   per level: h = gelu(conv1d(x, w1, k=3, s=1, p=1)) masked at len
//              y = conv1d(h, w2, k=3, s=2, p=1)        masked at ceil(len/2)
//   outputs: (feas_i [16,P_i,768], mask_i [16,P_i]) for P_i = 1024..1
//   last level (P=1, len=1): pooled == conv output, mask == 1 (degenerate).
// Layout: channel-last [b, p, c] everywhere => conv == implicit GEMM, K=2304.
// ---------------------------------------------------------------------------

#define CDIM 768
#define CK   2304        // 3 * 768
#define NLEV 11
#define BZ   16

// scratch (device globals: allocation-free rule)
__device__ float g_h[(long)BZ * 2048 * CDIM];   // gelu intermediate, max level
__device__ float g_wt1[CK * CDIM];              // w1 transposed: [d*768+i][o]
__device__ float g_wt2[CK * CDIM];

// ---------------------------------------------------------------------------
__global__ void transpose_weights(const float* __restrict__ w1,
                                  const float* __restrict__ w2) {
    int total = CK * CDIM;
    for (int j = blockIdx.x * blockDim.x + threadIdx.x; j < total;
         j += gridDim.x * blockDim.x) {
        int o  = j % CDIM;
        int kg = j / CDIM;          // d*768 + i
        int d  = kg / CDIM;
        int i  = kg - d * CDIM;
        long src = (long)o * CK + i * 3 + d;   // w[o][i][d]
        g_wt1[j] = w1[src];
        g_wt2[j] = w2[src];
    }
}

// ---------------------------------------------------------------------------
// write all 11 mask regions: mask_i[b,p] = (p < len_i) ? 1 : 0
__global__ void mask_kernel(float* __restrict__ out,
                            const int* __restrict__ lengths) {
    int idx    = blockIdx.x * blockDim.x + threadIdx.x;
    int stride = gridDim.x * blockDim.x;
    long off = 0;
    int P = 2048;
    for (int lvl = 0; lvl < NLEV; lvl++) {
        int Pout = (P - 1) / 2 + 1;
        long maskOff = off + (long)BZ * Pout * CDIM;
        int n = BZ * Pout;
        for (int i = idx; i < n; i += stride) {
            int b = i / Pout, p = i % Pout;
            int L = lengths[b];
            for (int t = 0; t <= lvl; t++) L = (L - 1) / 2 + 1;
            out[maskOff + i] = (p < L) ? 1.f : 0.f;
        }
        off = maskOff + n;
        P = Pout;
    }
}

// ---------------------------------------------------------------------------
// Implicit-GEMM conv. STRIDE=1 (conv1 + gelu, writes g_h) or 2 (conv2,
// reads g_h, writes Y). Tile: 64x64x16, 256 threads, 4x4 per thread.
template <int STRIDE, bool DO_GELU>
__global__ void __launch_bounds__(256)
conv_gemm(const float* __restrict__ X,      // conv1 input (unused for conv2)
          const float* __restrict__ bias,
          float* __restrict__ Y,            // conv2 output (unused for conv1)
          int Pin, int Pout,
          const int* __restrict__ lengths, int level) {
    constexpr int BM = 64, BN = 64, BK = 16;
    __shared__ float As[BK][BM + 4];   // +4 pad keeps 16B align, kills conflicts
    __shared__ float Bs[BK][BN];

    const int b   = blockIdx.z;
    const int p0  = blockIdx.x * BM;
    const int n0  = blockIdx.y * BN;
    const int tid = threadIdx.x;
    const int tx  = tid & 15;    // n-sub (4 cols each)
    const int ty  = tid >> 4;    // m-sub (4 rows each)

    // ragged length at this level
    int L = lengths[b];
    for (int t = 0; t < level; t++) L = (L - 1) / 2 + 1;
    const int lenIn  = (STRIDE == 1) ? L : Pin;           // g_h pre-zeroed tail
    const int lenOut = (STRIDE == 1) ? L : ((L - 1) / 2 + 1);

    const float* W   = DO_GELU ? g_wt1 : g_wt2;
    const float* Xsrc = (STRIDE == 1) ? X : (const float*)g_h;
    float*       Ydst = (STRIDE == 1) ? (float*)g_h : Y;
    const float* Xb  = Xsrc + (long)b * Pin * CDIM;

    float acc[4][4];
#pragma unroll
    for (int i = 0; i < 4; i++)
#pragma unroll
        for (int j = 0; j < 4; j++) acc[i][j] = 0.f;

    const int lm  = tid >> 4;    // A loader: row group
    const int lk  = tid & 15;    // A loader: k within chunk (=> channel, coalesced)
    const int ln  = tid & 63;    // B loader: col (coalesced)
    const int lkb = tid >> 6;    // B loader: k group

    for (int kk = 0; kk < CK; kk += BK) {
        const int d = kk / CDIM;                  // chunk never crosses tap bdry
        const int c = kk - d * CDIM + lk;
        // --- load A tile (implicit conv patch) ---
#pragma unroll
        for (int r = 0; r < 4; r++) {
            int m   = lm + r * 16;
            int pos = (p0 + m) * STRIDE + d - 1;
            float v = 0.f;
            if (pos >= 0 && pos < lenIn) v = Xb[(long)pos * CDIM + c];
            As[lk][m] = v;
        }
        // --- load B tile (pre-transposed weights, coalesced) ---
#pragma unroll
        for (int r = 0; r < 4; r++) {
            int k = lkb + r * 4;
            Bs[k][ln] = W[(long)(kk + k) * CDIM + n0 + ln];
        }
        __syncthreads();
#pragma unroll
        for (int k = 0; k < BK; k++) {
            float4 a  = *(const float4*)&As[k][ty * 4];
            float4 bq = *(const float4*)&Bs[k][tx * 4];
            acc[0][0] += a.x * bq.x; acc[0][1] += a.x * bq.y;
            acc[0][2] += a.x * bq.z; acc[0][3] += a.x * bq.w;
            acc[1][0] += a.y * bq.x; acc[1][1] += a.y * bq.y;
            acc[1][2] += a.y * bq.z; acc[1][3] += a.y * bq.w;
            acc[2][0] += a.z * bq.x; acc[2][1] += a.z * bq.y;
            acc[2][2] += a.z * bq.z; acc[2][3] += a.z * bq.w;
            acc[3][0] += a.w * bq.x; acc[3][1] += a.w * bq.y;
            acc[3][2] += a.w * bq.z; acc[3][3] += a.w * bq.w;
        }
        __syncthreads();
    }

    // --- epilogue: bias (+gelu), zero masked tail, coalesced float4 stores ---
    float* Yb = Ydst + (long)b * Pout * CDIM;
#pragma unroll
    for (int i = 0; i < 4; i++) {
        int p = p0 + ty * 4 + i;
        if (p >= Pout) continue;
        bool valid = (p < lenOut);
        float4 v;
        float* vp = &v.x;
#pragma unroll
        for (int j = 0; j < 4; j++) {
            int n = n0 + tx * 4 + j;
            float z = 0.f;
            if (valid) {
                z = acc[i][j] + bias[n];
                if (DO_GELU)
                    z = 0.5f * z * (1.f + erff(z * 0.7071067811865475f));
            }
            vp[j] = z;
        }
        *(float4*)&Yb[(long)p * CDIM + n0 + tx * 4] = v;
    }
}

// ---------------------------------------------------------------------------
extern "C" void kernel_launch(void* const* d_in, const int* in_sizes, int n_in,
                              void* d_out, int out_size) {
    const float* seq     = (const float*)d_in[0];   // [16,2048,768]
    const int*   lengths = (const int*)  d_in[1];   // [16]
    const float* w1      = (const float*)d_in[2];   // [768,768,3]
    const float* b1      = (const float*)d_in[3];   // [768]
    const float* w2      = (const float*)d_in[4];   // [768,768,3]
    const float* b2      = (const float*)d_in[5];   // [768]
    float* out = (float*)d_out;

    transpose_weights<<<256, 256>>>(w1, w2);
    mask_kernel<<<64, 256>>>(out, lengths);

    int P = 2048;
    const float* X = seq;
    long off = 0;
    for (int lvl = 0; lvl < NLEV; lvl++) {
        int Pout = (P - 1) / 2 + 1;
        dim3 g1((P + 63) / 64, CDIM / 64, BZ);
        conv_gemm<1, true><<<g1, 256>>>(X, b1, nullptr, P, P, lengths, lvl);
        dim3 g2((Pout + 63) / 64, CDIM / 64, BZ);
        conv_gemm<2, false><<<g2, 256>>>(nullptr, b2, out + off, P, Pout,
                                         lengths, lvl);
        X = out + off;                                   // next level input
        off += (long)BZ * Pout * CDIM + (long)BZ * Pout; // skip feas + mask
        P = Pout;
    }
}

// round 3
// speedup vs baseline: 2.2500x; 2.2500x over previous
#include <cuda_runtime.h>
#include <cuda_bf16.h>
#include <math.h>
#include <cstdint>

// ---------------------------------------------------------------------------
// TreeGetter: 11-level conv halving tree as implicit GEMM on mma.sync (bf16,
// hi/lo 3-product split for ~fp32 accuracy). M flattened = batch*P.
// conv1 (s=1) + exact GELU -> g_h ; conv2 (s=2) -> fp32 out + g_x (next lvl).
// ---------------------------------------------------------------------------

#define CDIM 768
#define CK   2304
#define NLEV 11
#define BZ   16
#define BM   128
#define BN   128
#define BKC  32
#define NCH  (CK / BKC)      // 72
#define STAGES 3

#define ASTRIDE 40           // bf16 elems per A row (32 + 8 pad) = 80B
#define BSTRIDE 136          // bf16 elems per B row (128 + 8 pad) = 272B
#define A_BYTES (BM * ASTRIDE * 2)            // 10240
#define B_BYTES (BKC * BSTRIDE * 2)           // 8704
#define STAGE_BYTES (2 * A_BYTES + 2 * B_BYTES)  // 37888
#define SMEM_BYTES (STAGES * STAGE_BYTES)        // 113664

// ---------------- scratch (device globals; allocation-free rule) ------------
#define MAXE ((long)BZ * 2048 * CDIM)
__device__ __nv_bfloat16 g_xhi[MAXE], g_xlo[MAXE];   // conv1 input splits
__device__ __nv_bfloat16 g_hhi[MAXE], g_hlo[MAXE];   // conv2 input splits
// weights transposed to [kg][o], kg = d*768 + i
__device__ __nv_bfloat16 g_w1hi[CK * CDIM], g_w1lo[CK * CDIM];
__device__ __nv_bfloat16 g_w2hi[CK * CDIM], g_w2lo[CK * CDIM];

__device__ __forceinline__ void split_bf16(float v, __nv_bfloat16& hi,
                                           __nv_bfloat16& lo) {
    hi = __float2bfloat16(v);
    lo = __float2bfloat16(v - __bfloat162float(hi));
}

__device__ __forceinline__ uint32_t smem_u32(const void* p) {
    uint32_t a;
    asm("{ .reg .u64 t; cvta.to.shared.u64 t, %1; cvt.u32.u64 %0, t; }"
        : "=r"(a) : "l"(p));
    return a;
}
__device__ __forceinline__ void cp_async16(uint32_t dst, const void* src,
                                           bool pred) {
    int sz = pred ? 16 : 0;
    asm volatile("cp.async.cg.shared.global [%0], [%1], 16, %2;"
                 :: "r"(dst), "l"(src), "r"(sz));
}
__device__ __forceinline__ void cp_commit() {
    asm volatile("cp.async.commit_group;");
}
__device__ __forceinline__ void ldsm_x4(uint32_t* r, uint32_t a) {
    asm volatile("ldmatrix.sync.aligned.m8n8.x4.shared.b16 {%0,%1,%2,%3}, [%4];"
                 : "=r"(r[0]), "=r"(r[1]), "=r"(r[2]), "=r"(r[3]) : "r"(a));
}
__device__ __forceinline__ void ldsm_x4_t(uint32_t* r, uint32_t a) {
    asm volatile("ldmatrix.sync.aligned.m8n8.x4.trans.shared.b16 {%0,%1,%2,%3}, [%4];"
                 : "=r"(r[0]), "=r"(r[1]), "=r"(r[2]), "=r"(r[3]) : "r"(a));
}
__device__ __forceinline__ void mma16816(float* d, const uint32_t* a,
                                         const uint32_t* b) {
    asm volatile(
        "mma.sync.aligned.m16n8k16.row.col.f32.bf16.bf16.f32 "
        "{%0,%1,%2,%3}, {%4,%5,%6,%7}, {%8,%9}, {%0,%1,%2,%3};"
        : "+f"(d[0]), "+f"(d[1]), "+f"(d[2]), "+f"(d[3])
        : "r"(a[0]), "r"(a[1]), "r"(a[2]), "r"(a[3]), "r"(b[0]), "r"(b[1]));
}

// ---------------------------------------------------------------------------
__global__ void prep_weights(const float* __restrict__ w1,
                             const float* __restrict__ w2) {
    int total = CK * CDIM;
    for (int j = blockIdx.x * blockDim.x + threadIdx.x; j < total;
         j += gridDim.x * blockDim.x) {
        int o  = j % CDIM;
        int kg = j / CDIM;
        int d  = kg / CDIM;
        int i  = kg - d * CDIM;
        long src = (long)o * CK + i * 3 + d;   // w[o][i][d]
        split_bf16(w1[src], g_w1hi[j], g_w1lo[j]);
        split_bf16(w2[src], g_w2hi[j], g_w2lo[j]);
    }
}

__global__ void prep_input(const float* __restrict__ seq,
                           const int* __restrict__ lengths) {
    long total = MAXE;
    for (long j = blockIdx.x * (long)blockDim.x + threadIdx.x; j < total;
         j += gridDim.x * (long)blockDim.x) {
        long bp = j / CDIM;
        int p = (int)(bp % 2048);
        int b = (int)(bp / 2048);
        float v = (p < lengths[b]) ? seq[j] : 0.f;
        split_bf16(v, g_xhi[j], g_xlo[j]);
    }
}

__global__ void mask_kernel(float* __restrict__ out,
                            const int* __restrict__ lengths) {
    int idx    = blockIdx.x * blockDim.x + threadIdx.x;
    int stride = gridDim.x * blockDim.x;
    long off = 0;
    int P = 2048;
    for (int lvl = 0; lvl < NLEV; lvl++) {
        int Pout = (P - 1) / 2 + 1;
        long maskOff = off + (long)BZ * Pout * CDIM;
        int n = BZ * Pout;
        for (int i = idx; i < n; i += stride) {
            int b = i / Pout, p = i % Pout;
            int L = lengths[b];
            for (int t = 0; t <= lvl; t++) L = (L - 1) / 2 + 1;
            out[maskOff + i] = (p < L) ? 1.f : 0.f;
        }
        off = maskOff + n;
        P = Pout;
    }
}

// ---------------------------------------------------------------------------
// Implicit-GEMM conv on mma.sync.  M rows flattened over (b, p).
// 256 threads = 8 warps (2 M x 4 N), warp tile 64x32, block 128x128x32.
template <int STRIDE, bool DO_GELU>
__global__ void __launch_bounds__(256, 1)
conv_mma(const float* __restrict__ bias, float* __restrict__ outY,
         int Pin, int Pout, const int* __restrict__ lengths, int level) {
    extern __shared__ char smem[];
    const uint32_t sbase = smem_u32(smem);
    const int tid   = threadIdx.x;
    const int lane  = tid & 31;
    const int wid   = tid >> 5;
    const int warpM = (wid & 1) * 64;
    const int warpN = (wid >> 1) * 32;
    const int p0    = blockIdx.x * BM;
    const int n0    = blockIdx.y * BN;
    const int Mtot  = BZ * Pout;

    const __nv_bfloat16* Xhi = DO_GELU ? g_xhi : g_hhi;
    const __nv_bfloat16* Xlo = DO_GELU ? g_xlo : g_hlo;
    const __nv_bfloat16* Whi = DO_GELU ? g_w1hi : g_w2hi;
    const __nv_bfloat16* Wlo = DO_GELU ? g_w1lo : g_w2lo;

    // ---- per-thread load geometry (fixed across stages) ----
    // A: id = tid + i*256 -> row = id>>2 (0..127), kc = id&3 (16B chunk)
    int aPosB[2]; long aRowBase[2]; bool aOk[2];
    const int akc = tid & 3;
#pragma unroll
    for (int i = 0; i < 2; i++) {
        int r = (tid + i * 256) >> 2;
        int grow = p0 + r;
        bool ok = grow < Mtot;
        int b = ok ? grow / Pout : 0;
        int p = grow - b * Pout;
        aOk[i] = ok;
        aPosB[i] = p * STRIDE - 1;
        aRowBase[i] = (long)b * Pin;
    }
    // B: id -> krow = id>>4 (0..31), nc = id&15
    const int bkrow0 = tid >> 4;           // +16 for second
    const int bnc = tid & 15;

    float acc[4][4][4];
#pragma unroll
    for (int a = 0; a < 4; a++)
#pragma unroll
        for (int b = 0; b < 4; b++)
#pragma unroll
            for (int c = 0; c < 4; c++) acc[a][b][c] = 0.f;

    // ldmatrix per-lane offsets (bytes)
    const uint32_t aoff =
        ((warpM + (lane & 15)) * ASTRIDE + ((lane >> 4) << 3)) * 2;
    const uint32_t boff =
        ((lane & 15) * BSTRIDE + warpN + ((lane >> 4) << 3)) * 2;

    // ---- stage loader ----
    auto load_stage = [&](int slot, int it) {
        const uint32_t sa = sbase + slot * STAGE_BYTES;
        const int kk = it * BKC;
        const int d  = (kk >= 1536) ? 2 : (kk >= 768 ? 1 : 0);
        const int c0 = kk - d * CDIM;
#pragma unroll
        for (int i = 0; i < 2; i++) {
            int id  = tid + i * 256;
            int row = id >> 2;
            int pos = aPosB[i] + d;
            bool v = aOk[i] && pos >= 0 && pos < Pin;
            long g = v ? ((aRowBase[i] + pos) * CDIM + c0 + akc * 8) : 0;
            uint32_t dst = sa + (row * ASTRIDE + akc * 8) * 2;
            cp_async16(dst, Xhi + g, v);
            cp_async16(dst + A_BYTES, Xlo + g, v);
        }
#pragma unroll
        for (int i = 0; i < 2; i++) {
            int krow = bkrow0 + i * 16;
            long g = (long)(kk + krow) * CDIM + n0 + bnc * 8;
            uint32_t dst = sa + 2 * A_BYTES + (krow * BSTRIDE + bnc * 8) * 2;
            cp_async16(dst, Whi + g, true);
            cp_async16(dst + B_BYTES, Wlo + g, true);
        }
        cp_commit();
    };

    // ---- pipeline ----
#pragma unroll
    for (int s = 0; s < STAGES - 1; s++) load_stage(s, s);

#pragma unroll 1
    for (int it = 0; it < NCH; it++) {
        int pre = it + STAGES - 1;
        if (pre < NCH) load_stage(pre % STAGES, pre);
        else cp_commit();
        asm volatile("cp.async.wait_group %0;" :: "n"(STAGES - 1));
        __syncthreads();

        const uint32_t sa = sbase + (it % STAGES) * STAGE_BYTES;
        const uint32_t aaddr = sa + aoff;
        const uint32_t baddr = sa + 2 * A_BYTES + boff;
#pragma unroll
        for (int ks2 = 0; ks2 < 2; ks2++) {
            const int ks = ks2 * 16;
            uint32_t ah[4][4], al[4][4], bh[2][4], bl[2][4];
#pragma unroll
            for (int mt = 0; mt < 4; mt++) {
                ldsm_x4(ah[mt], aaddr + (mt * 16 * ASTRIDE + ks) * 2);
                ldsm_x4(al[mt], aaddr + A_BYTES + (mt * 16 * ASTRIDE + ks) * 2);
            }
#pragma unroll
            for (int np = 0; np < 2; np++) {
                ldsm_x4_t(bh[np], baddr + (ks * BSTRIDE + np * 16) * 2);
                ldsm_x4_t(bl[np], baddr + B_BYTES + (ks * BSTRIDE + np * 16) * 2);
            }
#pragma unroll
            for (int mt = 0; mt < 4; mt++)
#pragma unroll
                for (int nt = 0; nt < 4; nt++) {
                    const uint32_t* h = &bh[nt >> 1][(nt & 1) * 2];
                    const uint32_t* l = &bl[nt >> 1][(nt & 1) * 2];
                    mma16816(acc[mt][nt], ah[mt], h);
                    mma16816(acc[mt][nt], ah[mt], l);
                    mma16816(acc[mt][nt], al[mt], h);
                }
        }
        __syncthreads();
    }

    // ---- epilogue ----
    const int mrow0 = p0 + warpM + (lane >> 2);
    const int colb  = n0 + warpN + 2 * (lane & 3);
#pragma unroll
    for (int mt = 0; mt < 4; mt++) {
#pragma unroll
        for (int half = 0; half < 2; half++) {
            int row = mrow0 + mt * 16 + half * 8;
            if (row >= Mtot) continue;
            int b = row / Pout;
            int p = row - b * Pout;
            int L = lengths[b];
            for (int t = 0; t < level; t++) L = (L - 1) / 2 + 1;
            int lenOut = DO_GELU ? L : ((L - 1) / 2 + 1);
            bool valid = p < lenOut;
            long base = (long)row * CDIM;
#pragma unroll
            for (int nt = 0; nt < 4; nt++) {
                int col = colb + nt * 8;
                float z0 = 0.f, z1 = 0.f;
                if (valid) {
                    z0 = acc[mt][nt][half * 2 + 0] + __ldg(&bias[col]);
                    z1 = acc[mt][nt][half * 2 + 1] + __ldg(&bias[col + 1]);
                    if (DO_GELU) {
                        z0 = 0.5f * z0 * (1.f + erff(z0 * 0.70710678118654752f));
                        z1 = 0.5f * z1 * (1.f + erff(z1 * 0.70710678118654752f));
                    }
                }
                __nv_bfloat162 h2, l2;
                split_bf16(z0, h2.x, l2.x);
                split_bf16(z1, h2.y, l2.y);
                if (DO_GELU) {
                    *(__nv_bfloat162*)(g_hhi + base + col) = h2;
                    *(__nv_bfloat162*)(g_hlo + base + col) = l2;
                } else {
                    float2 o2 = make_float2(z0, z1);
                    *(float2*)(outY + base + col) = o2;
                    *(__nv_bfloat162*)(g_xhi + base + col) = h2;
                    *(__nv_bfloat162*)(g_xlo + base + col) = l2;
                }
            }
        }
    }
}

// ---------------------------------------------------------------------------
extern "C" void kernel_launch(void* const* d_in, const int* in_sizes, int n_in,
                              void* d_out, int out_size) {
    const float* seq     = (const float*)d_in[0];
    const int*   lengths = (const int*)  d_in[1];
    const float* w1      = (const float*)d_in[2];
    const float* b1      = (const float*)d_in[3];
    const float* w2      = (const float*)d_in[4];
    const float* b2      = (const float*)d_in[5];
    float* out = (float*)d_out;

    cudaFuncSetAttribute(conv_mma<1, true>,
                         cudaFuncAttributeMaxDynamicSharedMemorySize, SMEM_BYTES);
    cudaFuncSetAttribute(conv_mma<2, false>,
                         cudaFuncAttributeMaxDynamicSharedMemorySize, SMEM_BYTES);

    prep_weights<<<256, 256>>>(w1, w2);
    prep_input<<<512, 256>>>(seq, lengths);
    mask_kernel<<<64, 256>>>(out, lengths);

    int P = 2048;
    long off = 0;
    for (int lvl = 0; lvl < NLEV; lvl++) {
        int Pout = (P - 1) / 2 + 1;
        dim3 g1((BZ * P + BM - 1) / BM, CDIM / BN);
        conv_mma<1, true><<<g1, 256, SMEM_BYTES>>>(b1, nullptr, P, P,
                                                   lengths, lvl);
        dim3 g2((BZ * Pout + BM - 1) / BM, CDIM / BN);
        conv_mma<2, false><<<g2, 256, SMEM_BYTES>>>(b2, out + off, P, Pout,
                                                    lengths, lvl);
        off += (long)BZ * Pout * CDIM + (long)BZ * Pout;
        P = Pout;
    }
}